// round 13
// baseline (speedup 1.0000x reference)
#include <cuda_runtime.h>
#include <cuda_bf16.h>
#include <math.h>
#include <stdint.h>

#define SQ   3072
#define HIDD 1152
#define NHD  16
#define HDIM 72
#define MLPD 4304
#define MLPP 4352
#define T3   3456
#define EPSLN 1e-5f

// ---------------- scratch (allocation-free: __device__ globals) ----------------
__device__ unsigned short g_hh[SQ * HIDD], g_hl[SQ * HIDD];
__device__ unsigned short g_qkvh[SQ * T3], g_qkvl[SQ * T3];
__device__ unsigned short g_atth[SQ * HIDD], g_attl[SQ * HIDD];
__device__ float g_y1[SQ * HIDD];
__device__ unsigned short g_mlph[(size_t)SQ * MLPP], g_mlpl[(size_t)SQ * MLPP];
__device__ unsigned short g_wqkvt_h[(size_t)T3 * HIDD], g_wqkvt_l[(size_t)T3 * HIDD];
__device__ unsigned short g_wot_h[HIDD * HIDD], g_wot_l[HIDD * HIDD];
__device__ unsigned short g_w1t_h[(size_t)MLPP * HIDD], g_w1t_l[(size_t)MLPP * HIDD];
__device__ unsigned short g_w2t_h[(size_t)HIDD * MLPP], g_w2t_l[(size_t)HIDD * MLPP];
__device__ int g_seg[SQ];

// ---------------- helpers ----------------
__device__ __forceinline__ uint32_t smem_u32(const void* p) {
    uint32_t a;
    asm("{ .reg .u64 t; cvta.to.shared.u64 t, %1; cvt.u32.u64 %0, t; }" : "=r"(a) : "l"(p));
    return a;
}
__device__ __forceinline__ void ldsm4(uint32_t r[4], uint32_t a) {
    asm volatile("ldmatrix.sync.aligned.m8n8.x4.shared.b16 {%0,%1,%2,%3}, [%4];"
                 : "=r"(r[0]), "=r"(r[1]), "=r"(r[2]), "=r"(r[3]) : "r"(a));
}
__device__ __forceinline__ void ldsm4t(uint32_t r[4], uint32_t a) {
    asm volatile("ldmatrix.sync.aligned.m8n8.x4.trans.shared.b16 {%0,%1,%2,%3}, [%4];"
                 : "=r"(r[0]), "=r"(r[1]), "=r"(r[2]), "=r"(r[3]) : "r"(a));
}
__device__ __forceinline__ void mma16816(float d[4], const uint32_t a[4], const uint32_t b[2]) {
    asm volatile(
        "mma.sync.aligned.m16n8k16.row.col.f32.bf16.bf16.f32 "
        "{%0,%1,%2,%3}, {%4,%5,%6,%7}, {%8,%9}, {%0,%1,%2,%3};"
        : "+f"(d[0]), "+f"(d[1]), "+f"(d[2]), "+f"(d[3])
        : "r"(a[0]), "r"(a[1]), "r"(a[2]), "r"(a[3]), "r"(b[0]), "r"(b[1]));
}
__device__ __forceinline__ void cpasync16(uint32_t dst, const void* src) {
    asm volatile("cp.async.cg.shared.global [%0], [%1], 16;" :: "r"(dst), "l"(src));
}
#define CP_COMMIT() asm volatile("cp.async.commit_group;" ::: "memory")
#define CP_WAIT(n)  asm volatile("cp.async.wait_group %0;" :: "n"(n) : "memory")

__device__ __forceinline__ void split_bf(float f, unsigned short& h, unsigned short& l) {
    __nv_bfloat16 hb = __float2bfloat16(f);
    float r = f - __bfloat162float(hb);
    __nv_bfloat16 lb = __float2bfloat16(r);
    h = __bfloat16_as_ushort(hb);
    l = __bfloat16_as_ushort(lb);
}
__device__ __forceinline__ void packsplit(float a, float b, uint32_t& hi, uint32_t& lo) {
    unsigned short ha, la, hb, lb;
    split_bf(a, ha, la);
    split_bf(b, hb, lb);
    hi = (uint32_t)ha | ((uint32_t)hb << 16);
    lo = (uint32_t)la | ((uint32_t)lb << 16);
}
__device__ __forceinline__ float gelu_tanh(float x) {
    float x3 = x * x * x;
    return 0.5f * x * (1.0f + tanhf(0.7978845608028654f * (x + 0.044715f * x3)));
}

// ---------------- weight convert+transpose: W (K x N fp32) -> Th,Tl (N x Kt bf16) ----------------
__global__ void convtrans(const float* __restrict__ W, int K, int N,
                          unsigned short* __restrict__ Th, unsigned short* __restrict__ Tl, int Kt) {
    __shared__ float t[32][33];
    int k0 = blockIdx.y * 32, n0 = blockIdx.x * 32;
    int tx = threadIdx.x, ty = threadIdx.y;  // 32 x 8
    #pragma unroll
    for (int i = 0; i < 4; i++) {
        int k = k0 + ty + i * 8, n = n0 + tx;
        t[ty + i * 8][tx] = (k < K && n < N) ? W[(size_t)k * N + n] : 0.f;
    }
    __syncthreads();
    #pragma unroll
    for (int i = 0; i < 4; i++) {
        int n = n0 + ty + i * 8, k = k0 + tx;
        if (n < N && k < K) {
            unsigned short h, l;
            split_bf(t[tx][ty + i * 8], h, l);
            Th[(size_t)n * Kt + k] = h;
            Tl[(size_t)n * Kt + k] = l;
        }
    }
}

// ================= pure-bf16 3-term split GEMM, 512 threads, cp.async 3-stage =================
// MODE 1: bf16 hi/lo gelu(+bias)   MODE 3: fp32 +bias+resid
// MODE 4: +bias, RoPE on cols<2*HIDD (aux = freqs_cis), bf16 hi/lo out
#define GB_SMEM (3 * 65536)

template <int MODE>
__global__ void __launch_bounds__(512, 1)
gemm_bf(int N, int Kp,
        const unsigned short* __restrict__ Ah_, const unsigned short* __restrict__ Al_,
        const unsigned short* __restrict__ Bh_, const unsigned short* __restrict__ Bl_,
        float* __restrict__ C, int ldc,
        unsigned short* __restrict__ OH, unsigned short* __restrict__ OL, int ldo,
        const float* __restrict__ bias,
        const float* __restrict__ aux, int ldr) {
    extern __shared__ char smbuf[];
    const uint32_t sb = smem_u32(smbuf);
    const int tid = threadIdx.x, lane = tid & 31, wid = tid >> 5;
    const int wm = wid & 3, wn = wid >> 2;           // 4 x 4 warps, 32x32 warp tile
    const int m0 = blockIdx.y * 128, n0 = blockIdx.x * 128;
    const int nc = Kp >> 6;

    auto issue = [&](int c) {
        uint32_t stb = sb + (uint32_t)(c % 3) * 65536u;
        int k0 = c << 6;
        #pragma unroll
        for (int i = 0; i < 2; i++) {
            int idx = tid + 512 * i;           // 0..1023
            int row = idx >> 3, col = idx & 7;
            uint32_t d = stb + (uint32_t)row * 128u + (((uint32_t)col * 16u) ^ (((uint32_t)row & 7u) << 4));
            size_t ao = (size_t)(m0 + row) * Kp + k0 + col * 8;
            size_t bo = (size_t)(n0 + row) * Kp + k0 + col * 8;
            cpasync16(d,          Ah_ + ao);
            cpasync16(d + 16384u, Al_ + ao);
            cpasync16(d + 32768u, Bh_ + bo);
            cpasync16(d + 49152u, Bl_ + bo);
        }
    };

    float acc[2][4][4];
    #pragma unroll
    for (int mi = 0; mi < 2; mi++)
        #pragma unroll
        for (int ni = 0; ni < 4; ni++)
            #pragma unroll
            for (int e = 0; e < 4; e++) acc[mi][ni][e] = 0.f;

    const uint32_t ra = (uint32_t)(wm * 32 + (lane & 15));
    const uint32_t xa = (ra & 7u) << 4;
    const uint32_t ca = (uint32_t)((lane >> 4) * 16);
    const uint32_t rb = (uint32_t)(wn * 32 + ((lane >> 4) << 3) + (lane & 7));
    const uint32_t xb = (rb & 7u) << 4;
    const uint32_t cb = (uint32_t)(((lane >> 3) & 1) * 16);

    issue(0); CP_COMMIT();
    issue(1); CP_COMMIT();

    for (int c = 0; c < nc; c++) {
        if (c == nc - 1) { CP_WAIT(0); } else { CP_WAIT(1); }
        __syncthreads();
        if (c + 2 < nc) { issue(c + 2); CP_COMMIT(); }

        const uint32_t stb = sb + (uint32_t)(c % 3) * 65536u;
        #pragma unroll
        for (int kk = 0; kk < 4; kk++) {
            uint32_t ah[2][4], al[2][4], bh[4][2], bl[4][2];
            #pragma unroll
            for (int mi = 0; mi < 2; mi++) {
                uint32_t ad = stb + (ra + mi * 16u) * 128u + ((ca + kk * 32u) ^ xa);
                ldsm4(ah[mi], ad);
                ldsm4(al[mi], ad + 16384u);
            }
            #pragma unroll
            for (int nj = 0; nj < 2; nj++) {
                uint32_t t[4];
                uint32_t bd = stb + 32768u + (rb + nj * 16u) * 128u + ((cb + kk * 32u) ^ xb);
                ldsm4(t, bd);
                bh[2 * nj][0] = t[0]; bh[2 * nj][1] = t[1];
                bh[2 * nj + 1][0] = t[2]; bh[2 * nj + 1][1] = t[3];
                ldsm4(t, bd + 16384u);
                bl[2 * nj][0] = t[0]; bl[2 * nj][1] = t[1];
                bl[2 * nj + 1][0] = t[2]; bl[2 * nj + 1][1] = t[3];
            }
            #pragma unroll
            for (int mi = 0; mi < 2; mi++)
                #pragma unroll
                for (int ni = 0; ni < 4; ni++)
                    mma16816(acc[mi][ni], ah[mi], bh[ni]);
            #pragma unroll
            for (int mi = 0; mi < 2; mi++)
                #pragma unroll
                for (int ni = 0; ni < 4; ni++)
                    mma16816(acc[mi][ni], ah[mi], bl[ni]);
            #pragma unroll
            for (int mi = 0; mi < 2; mi++)
                #pragma unroll
                for (int ni = 0; ni < 4; ni++)
                    mma16816(acc[mi][ni], al[mi], bh[ni]);
        }
    }

    // ---- epilogue ----
    const int tr = lane >> 2;
    const int tc2 = (lane & 3) * 2;
    #pragma unroll
    for (int mi = 0; mi < 2; mi++) {
        #pragma unroll
        for (int h2 = 0; h2 < 2; h2++) {
            int row = m0 + wm * 32 + mi * 16 + h2 * 8 + tr;
            float* crow = (MODE == 3) ? C + (size_t)row * ldc : nullptr;
            const float* rrow = (MODE == 3) ? aux + (size_t)row * ldr : nullptr;
            #pragma unroll
            for (int ni = 0; ni < 4; ni++) {
                int col = n0 + wn * 32 + ni * 8 + tc2;
                if (col < N) {
                    float v0 = acc[mi][ni][2 * h2];
                    float v1 = acc[mi][ni][2 * h2 + 1];
                    if (MODE == 1) {
                        v0 = gelu_tanh(v0 + bias[col]);
                        v1 = gelu_tanh(v1 + bias[col + 1]);
                        uint32_t hp, lp;
                        packsplit(v0, v1, hp, lp);
                        *(uint32_t*)(OH + (size_t)row * ldo + col) = hp;
                        *(uint32_t*)(OL + (size_t)row * ldo + col) = lp;
                    } else if (MODE == 3) {
                        v0 += bias[col] + rrow[col];
                        v1 += bias[col + 1] + rrow[col + 1];
                        *(float2*)(crow + col) = make_float2(v0, v1);
                    } else if (MODE == 4) {
                        v0 += bias[col];
                        v1 += bias[col + 1];
                        if (col < 2 * HIDD) {
                            int hd = (col % HIDD) % HDIM;
                            float2 cs = *(const float2*)(aux + (size_t)row * HDIM + hd);
                            float ra2 = v0 * cs.x - v1 * cs.y;
                            float rb2 = v0 * cs.y + v1 * cs.x;
                            v0 = ra2; v1 = rb2;
                        }
                        uint32_t hp, lp;
                        packsplit(v0, v1, hp, lp);
                        *(uint32_t*)(OH + (size_t)row * ldo + col) = hp;
                        *(uint32_t*)(OL + (size_t)row * ldo + col) = lp;
                    }
                }
            }
        }
    }
}

// ================= fused flash attention: 512 threads, 256 queries/CTA, 64-key tiles =================
// smem: Qh(256x176) Ql(256x176) resident + 2 stages x {Kh,Kl,Vh,Vl 64x176} + segk
#define VSTR   176
#define QTILE  (256 * VSTR)          // 45056
#define KTILE  (64 * VSTR)           // 11264
#define KVOFF  (2 * QTILE)           // 90112
#define KVSTG  (4 * KTILE)           // 45056
#define SEGOFF (KVOFF + 2 * KVSTG)   // 180224
#define FA_SMEM (SEGOFF + 512)
#define ALPHA_ATT 0.11785113019775793f
#define NKT (SQ / 64)                // 48

__global__ void __launch_bounds__(512, 1)
flash_attn(const unsigned short* __restrict__ qkvh,
           const unsigned short* __restrict__ qkvl,
           const int* __restrict__ seg,
           unsigned short* __restrict__ atth,
           unsigned short* __restrict__ attl) {
    extern __shared__ char smf[];
    const int tid = threadIdx.x, lane = tid & 31, wid = tid >> 5;   // 16 warps
    const int m0 = blockIdx.x * 256;
    const int hh = blockIdx.y;
    const int qcol = hh * HDIM;
    const uint32_t sb = smem_u32(smf);

    // ---- zero pad bytes 144..159 of every 176B row across [0, SEGOFF) ----
    {
        uint4 z = make_uint4(0, 0, 0, 0);
        #pragma unroll
        for (int i = 0; i < 2; i++) {
            int r = tid + 512 * i;                 // 0..1023 rows
            *(uint4*)(smf + (size_t)r * VSTR + 144) = z;
        }
    }

    // ---- stage Q (hi tile, lo tile) via cp.async ----
    {
        #pragma unroll
        for (int i = 0; i < 9; i++) {
            int idx = tid + 512 * i;               // 0..4607
            int tile = idx / 2304;
            int rem = idx - tile * 2304;
            int r = rem / 9, cc = rem - r * 9;
            const unsigned short* src = (tile ? qkvl : qkvh) + (size_t)(m0 + r) * T3 + qcol + cc * 8;
            cpasync16(sb + (uint32_t)tile * QTILE + (uint32_t)r * VSTR + cc * 16, src);
        }
        CP_COMMIT();
        CP_WAIT(0);
    }
    __syncthreads();

    // ---- Q fragments (registers, whole kernel) ----
    uint32_t qh[5][4], ql[5][4];
    {
        uint32_t qa = sb + (uint32_t)(wid * 16 + (lane & 15)) * VSTR + (lane >> 4) * 16;
        #pragma unroll
        for (int kc = 0; kc < 5; kc++) {
            ldsm4(qh[kc], qa + kc * 32);
            ldsm4(ql[kc], qa + QTILE + kc * 32);
        }
    }

    #define KV_ISSUE(kt_)  do {                                                       \
        int n0_ = (kt_) * 64;                                                         \
        uint32_t dstb_ = sb + KVOFF + (uint32_t)((kt_) & 1) * KVSTG;                  \
        const unsigned short* b0_ = qkvh + (size_t)n0_ * T3 + HIDD + qcol;            \
        const unsigned short* b1_ = qkvl + (size_t)n0_ * T3 + HIDD + qcol;            \
        const unsigned short* b2_ = b0_ + HIDD;                                       \
        const unsigned short* b3_ = b1_ + HIDD;                                       \
        _Pragma("unroll")                                                             \
        for (int i = 0; i < 5; i++) {                                                 \
            int idx = tid + 512 * i;                                                  \
            if (idx < 2304) {                                                         \
                int tile = idx / 576;                                                 \
                int rem = idx - tile * 576;                                           \
                int r = rem / 9, cc = rem - r * 9;                                    \
                const unsigned short* src =                                           \
                    (tile == 0 ? b0_ : tile == 1 ? b1_ : tile == 2 ? b2_ : b3_)       \
                    + (size_t)r * T3 + cc * 8;                                        \
                cpasync16(dstb_ + (uint32_t)tile * KTILE + (uint32_t)r * VSTR + cc * 16, src); \
            }                                                                         \
        }                                                                             \
        if (tid < 64)                                                                 \
            *(int*)(smf + SEGOFF + ((kt_) & 1) * 256 + tid * 4) = seg[n0_ + tid];     \
        CP_COMMIT();                                                                  \
    } while (0)

    KV_ISSUE(0);
    KV_ISSUE(1);

    const int tr = lane >> 2, tc = lane & 3;
    const int segq0 = seg[m0 + wid * 16 + tr];
    const int segq1 = seg[m0 + wid * 16 + tr + 8];

    float mr0 = -1e30f, mr1 = -1e30f;
    float el0 = 0.f, el1 = 0.f;
    float o[9][4];
    #pragma unroll
    for (int f = 0; f < 9; f++)
        #pragma unroll
        for (int e = 0; e < 4; e++) o[f][e] = 0.f;

    for (int kt = 0; kt < NKT; kt++) {
        if (kt == NKT - 1) { CP_WAIT(0); } else { CP_WAIT(1); }
        __syncthreads();

        const uint32_t kvb = sb + KVOFF + (uint32_t)(kt & 1) * KVSTG;
        const int* segk = (const int*)(smf + SEGOFF + (kt & 1) * 256);

        // ---- S = Q K^T over 64 keys (3-term) ----
        float s[8][4];
        #pragma unroll
        for (int ni = 0; ni < 8; ni++)
            #pragma unroll
            for (int e = 0; e < 4; e++) s[ni][e] = 0.f;

        #pragma unroll
        for (int kc = 0; kc < 5; kc++) {
            #pragma unroll
            for (int nj = 0; nj < 4; nj++) {
                uint32_t bh4[4], bl4[4];
                uint32_t kb = kvb + (uint32_t)(nj * 16 + ((lane >> 4) << 3) + (lane & 7)) * VSTR
                              + ((lane >> 3) & 1) * 16 + kc * 32;
                ldsm4(bh4, kb);
                ldsm4(bl4, kb + KTILE);
                mma16816(s[2 * nj],     qh[kc], bh4);
                mma16816(s[2 * nj],     qh[kc], bl4);
                mma16816(s[2 * nj],     ql[kc], bh4);
                mma16816(s[2 * nj + 1], qh[kc], bh4 + 2);
                mma16816(s[2 * nj + 1], qh[kc], bl4 + 2);
                mma16816(s[2 * nj + 1], ql[kc], bh4 + 2);
            }
        }

        // ---- alpha scale + segment bias + online softmax ----
        float rm0 = -1e30f, rm1 = -1e30f;
        #pragma unroll
        for (int ni = 0; ni < 8; ni++) {
            int sk0 = segk[ni * 8 + 2 * tc];
            int sk1 = segk[ni * 8 + 2 * tc + 1];
            s[ni][0] = fmaf(s[ni][0], ALPHA_ATT, (segq0 == sk0) ? 1.f : 0.f);
            s[ni][1] = fmaf(s[ni][1], ALPHA_ATT, (segq0 == sk1) ? 1.f : 0.f);
            s[ni][2] = fmaf(s[ni][2], ALPHA_ATT, (segq1 == sk0) ? 1.f : 0.f);
            s[ni][3] = fmaf(s[ni][3], ALPHA_ATT, (segq1 == sk1) ? 1.f : 0.f);
            rm0 = fmaxf(rm0, fmaxf(s[ni][0], s[ni][1]));
            rm1 = fmaxf(rm1, fmaxf(s[ni][2], s[ni][3]));
        }
        rm0 = fmaxf(rm0, __shfl_xor_sync(0xffffffffu, rm0, 1));
        rm0 = fmaxf(rm0, __shfl_xor_sync(0xffffffffu, rm0, 2));
        rm1 = fmaxf(rm1, __shfl_xor_sync(0xffffffffu, rm1, 1));
        rm1 = fmaxf(rm1, __shfl_xor_sync(0xffffffffu, rm1, 2));
        float mn0 = fmaxf(mr0, rm0), mn1 = fmaxf(mr1, rm1);
        float sc0 = __expf(mr0 - mn0), sc1 = __expf(mr1 - mn1);
        mr0 = mn0; mr1 = mn1;
        float rs0 = 0.f, rs1 = 0.f;
        #pragma unroll
        for (int ni = 0; ni < 8; ni++) {
            s[ni][0] = __expf(s[ni][0] - mn0); rs0 += s[ni][0];
            s[ni][1] = __expf(s[ni][1] - mn0); rs0 += s[ni][1];
            s[ni][2] = __expf(s[ni][2] - mn1); rs1 += s[ni][2];
            s[ni][3] = __expf(s[ni][3] - mn1); rs1 += s[ni][3];
        }
        rs0 += __shfl_xor_sync(0xffffffffu, rs0, 1);
        rs0 += __shfl_xor_sync(0xffffffffu, rs0, 2);
        rs1 += __shfl_xor_sync(0xffffffffu, rs1, 1);
        rs1 += __shfl_xor_sync(0xffffffffu, rs1, 2);
        el0 = el0 * sc0 + rs0;
        el1 = el1 * sc1 + rs1;
        #pragma unroll
        for (int f = 0; f < 9; f++) {
            o[f][0] *= sc0; o[f][1] *= sc0;
            o[f][2] *= sc1; o[f][3] *= sc1;
        }

        // ---- O += P V (3-term), V rows = 64 keys ----
        #pragma unroll
        for (int kc2 = 0; kc2 < 4; kc2++) {
            uint32_t ph[4], pl[4];
            packsplit(s[2 * kc2][0],     s[2 * kc2][1],     ph[0], pl[0]);
            packsplit(s[2 * kc2][2],     s[2 * kc2][3],     ph[1], pl[1]);
            packsplit(s[2 * kc2 + 1][0], s[2 * kc2 + 1][1], ph[2], pl[2]);
            packsplit(s[2 * kc2 + 1][2], s[2 * kc2 + 1][3], ph[3], pl[3]);
            #pragma unroll
            for (int vj = 0; vj < 5; vj++) {
                uint32_t vh4[4], vl4[4];
                uint32_t va = kvb + 2 * KTILE
                              + (uint32_t)(kc2 * 16 + (lane & 15)) * VSTR
                              + (uint32_t)(vj * 16 + (lane >> 4) * 8) * 2;
                ldsm4t(vh4, va);
                ldsm4t(vl4, va + KTILE);
                mma16816(o[2 * vj], ph, vh4);
                mma16816(o[2 * vj], ph, vl4);
                mma16816(o[2 * vj], pl, vh4);
                if (vj < 4) {
                    mma16816(o[2 * vj + 1], ph, vh4 + 2);
                    mma16816(o[2 * vj + 1], ph, vl4 + 2);
                    mma16816(o[2 * vj + 1], pl, vh4 + 2);
                }
            }
        }

        __syncthreads();                    // all warps done with buffer kt&1
        if (kt + 2 < NKT) KV_ISSUE(kt + 2);
    }

    // ---- normalize, split, store bf16 hi/lo ----
    float i0 = 1.f / el0, i1 = 1.f / el1;
    int row0 = m0 + wid * 16 + tr;
    size_t ob0 = (size_t)row0 * HIDD + qcol;
    size_t ob1 = ob0 + (size_t)8 * HIDD;
    #pragma unroll
    for (int f = 0; f < 9; f++) {
        int col = f * 8 + 2 * tc;
        uint32_t hp, lp;
        packsplit(o[f][0] * i0, o[f][1] * i0, hp, lp);
        *(uint32_t*)(atth + ob0 + col) = hp;
        *(uint32_t*)(attl + ob0 + col) = lp;
        packsplit(o[f][2] * i1, o[f][3] * i1, hp, lp);
        *(uint32_t*)(atth + ob1 + col) = hp;
        *(uint32_t*)(attl + ob1 + col) = lp;
    }
    #undef KV_ISSUE
}

// ---------------- layernorm -> bf16 hi/lo ----------------
__global__ void ln_kernel(const float* __restrict__ x,
                          const float* __restrict__ g,
                          const float* __restrict__ b,
                          unsigned short* __restrict__ oh,
                          unsigned short* __restrict__ ol) {
    int row = blockIdx.x;
    const float* xr = x + (size_t)row * HIDD;
    float s1 = 0.f, s2 = 0.f;
    for (int i = threadIdx.x; i < HIDD; i += blockDim.x) {
        float v = xr[i];
        s1 += v; s2 += v * v;
    }
    __shared__ float sh1[8], sh2[8];
    #pragma unroll
    for (int o2 = 16; o2; o2 >>= 1) {
        s1 += __shfl_xor_sync(0xffffffffu, s1, o2);
        s2 += __shfl_xor_sync(0xffffffffu, s2, o2);
    }
    int w = threadIdx.x >> 5, l = threadIdx.x & 31;
    if (l == 0) { sh1[w] = s1; sh2[w] = s2; }
    __syncthreads();
    if (w == 0) {
        s1 = (l < 8) ? sh1[l] : 0.f;
        s2 = (l < 8) ? sh2[l] : 0.f;
        #pragma unroll
        for (int o2 = 4; o2; o2 >>= 1) {
            s1 += __shfl_xor_sync(0xffffffffu, s1, o2);
            s2 += __shfl_xor_sync(0xffffffffu, s2, o2);
        }
        if (l == 0) { sh1[0] = s1; sh2[0] = s2; }
    }
    __syncthreads();
    float mu = sh1[0] * (1.0f / HIDD);
    float var = sh2[0] * (1.0f / HIDD) - mu * mu;
    float rs = rsqrtf(var + EPSLN);
    for (int i = threadIdx.x; i < HIDD; i += blockDim.x) {
        float v = (xr[i] - mu) * rs * g[i] + b[i];
        unsigned short hv, lv;
        split_bf(v, hv, lv);
        oh[(size_t)row * HIDD + i] = hv;
        ol[(size_t)row * HIDD + i] = lv;
    }
}

// ---------------- segment ids ----------------
__global__ void seg_kernel(const int* __restrict__ off, int n, int* __restrict__ seg) {
    int t = blockIdx.x * blockDim.x + threadIdx.x;
    if (t >= SQ) return;
    int s = 0;
    for (int i = 1; i < n; i++)
        if (t >= off[i]) s = i;
    seg[t] = s;
}

// ---------------- launcher ----------------
extern "C" void kernel_launch(void* const* d_in, const int* in_sizes, int n_in,
                              void* d_out, int out_size) {
    const float* x      = (const float*)d_in[0];
    const int*   offs   = (const int*)d_in[1];
    const float* fc     = (const float*)d_in[2];
    const float* ln0_g  = (const float*)d_in[3];
    const float* ln0_b  = (const float*)d_in[4];
    const float* wqkv_w = (const float*)d_in[5];
    const float* wqkv_b = (const float*)d_in[6];
    const float* wo_w   = (const float*)d_in[7];
    const float* wo_b   = (const float*)d_in[8];
    const float* ln1_g  = (const float*)d_in[9];
    const float* ln1_b  = (const float*)d_in[10];
    const float* w1     = (const float*)d_in[11];
    const float* b1     = (const float*)d_in[12];
    const float* w2     = (const float*)d_in[13];
    const float* b2     = (const float*)d_in[14];
    float* out = (float*)d_out;

    unsigned short *hh, *hl, *qkvh, *qkvl, *atth, *attl, *mlph, *mlpl;
    unsigned short *wqt_h, *wqt_l, *wot_h, *wot_l, *w1t_h, *w1t_l, *w2t_h, *w2t_l;
    float *y1;
    int* seg;
    cudaGetSymbolAddress((void**)&hh, g_hh);
    cudaGetSymbolAddress((void**)&hl, g_hl);
    cudaGetSymbolAddress((void**)&qkvh, g_qkvh);
    cudaGetSymbolAddress((void**)&qkvl, g_qkvl);
    cudaGetSymbolAddress((void**)&atth, g_atth);
    cudaGetSymbolAddress((void**)&attl, g_attl);
    cudaGetSymbolAddress((void**)&y1, g_y1);
    cudaGetSymbolAddress((void**)&mlph, g_mlph);
    cudaGetSymbolAddress((void**)&mlpl, g_mlpl);
    cudaGetSymbolAddress((void**)&wqt_h, g_wqkvt_h);
    cudaGetSymbolAddress((void**)&wqt_l, g_wqkvt_l);
    cudaGetSymbolAddress((void**)&wot_h, g_wot_h);
    cudaGetSymbolAddress((void**)&wot_l, g_wot_l);
    cudaGetSymbolAddress((void**)&w1t_h, g_w1t_h);
    cudaGetSymbolAddress((void**)&w1t_l, g_w1t_l);
    cudaGetSymbolAddress((void**)&w2t_h, g_w2t_h);
    cudaGetSymbolAddress((void**)&w2t_l, g_w2t_l);
    cudaGetSymbolAddress((void**)&seg, g_seg);

    cudaFuncSetAttribute(gemm_bf<1>, cudaFuncAttributeMaxDynamicSharedMemorySize, GB_SMEM);
    cudaFuncSetAttribute(gemm_bf<3>, cudaFuncAttributeMaxDynamicSharedMemorySize, GB_SMEM);
    cudaFuncSetAttribute(gemm_bf<4>, cudaFuncAttributeMaxDynamicSharedMemorySize, GB_SMEM);
    cudaFuncSetAttribute(flash_attn, cudaFuncAttributeMaxDynamicSharedMemorySize, FA_SMEM);

    int n_off = in_sizes[1];
    dim3 ctb(32, 8);

    // 0. weight convert+transpose
    convtrans<<<dim3(T3 / 32, HIDD / 32), ctb>>>(wqkv_w, HIDD, T3, wqt_h, wqt_l, HIDD);
    convtrans<<<dim3(HIDD / 32, HIDD / 32), ctb>>>(wo_w, HIDD, HIDD, wot_h, wot_l, HIDD);
    convtrans<<<dim3((MLPD + 31) / 32, HIDD / 32), ctb>>>(w1, HIDD, MLPD, w1t_h, w1t_l, HIDD);
    convtrans<<<dim3(HIDD / 32, (MLPD + 31) / 32), ctb>>>(w2, MLPD, HIDD, w2t_h, w2t_l, MLPP);

    // 1. LN0 -> h (bf16 hi/lo)
    ln_kernel<<<SQ, 256>>>(x, ln0_g, ln0_b, hh, hl);

    // 2. segment ids
    seg_kernel<<<(SQ + 255) / 256, 256>>>(offs, n_off, seg);

    // 3. QKV = h @ Wqkv + b, fused RoPE + bf16 split -> qkvh/qkvl
    gemm_bf<4><<<dim3(T3 / 128, SQ / 128), 512, GB_SMEM>>>(
        T3, HIDD, hh, hl, wqt_h, wqt_l, nullptr, 0,
        qkvh, qkvl, T3, wqkv_b, fc, 0);

    // 4. fused attention -> att (bf16 hi/lo)
    flash_attn<<<dim3(SQ / 256, NHD), 512, FA_SMEM>>>(qkvh, qkvl, seg, atth, attl);

    // 5. y1 = x + att @ Wo + b
    gemm_bf<3><<<dim3(HIDD / 128, SQ / 128), 512, GB_SMEM>>>(
        HIDD, HIDD, atth, attl, wot_h, wot_l, y1, HIDD,
        nullptr, nullptr, 0, wo_b, x, HIDD);

    // 6. LN1 -> h (bf16 hi/lo)
    ln_kernel<<<SQ, 256>>>(y1, ln1_g, ln1_b, hh, hl);

    // 7. mlp = gelu(h @ W1 + b1) -> bf16 hi/lo (padded to 4352)
    gemm_bf<1><<<dim3(MLPP / 128, SQ / 128), 512, GB_SMEM>>>(
        MLPD, HIDD, hh, hl, w1t_h, w1t_l, nullptr, 0,
        mlph, mlpl, MLPP, b1, nullptr, 0);

    // 8. out = y1 + mlp @ W2 + b2
    gemm_bf<3><<<dim3(HIDD / 128, SQ / 128), 512, GB_SMEM>>>(
        HIDD, MLPP, mlph, mlpl, w2t_h, w2t_l, out, HIDD,
        nullptr, nullptr, 0, b2, y1, HIDD);
}